// round 4
// baseline (speedup 1.0000x reference)
#include <cuda_runtime.h>
#include <math.h>

#define NSEQ  256     // B*S
#define TSEQ  128
#define EMBED 512
#define UNITS 512
#define G4    2048    // 4*UNITS

// ---------------- scratch (allocation-free: __device__ globals) ----------------
// xW[dir][step][n][gatecol]  (backward dir stored already time-reversed)
__device__ float g_xW[2][TSEQ][NSEQ][G4];        // 512 MB
// h/c double-buffered per direction: [dir][buf][n][unit]
__device__ float g_h[2][2][NSEQ][UNITS];
__device__ float g_c[2][2][NSEQ][UNITS];

// =====================================================================
// Kernel 1: fused embedding-gather + input projection GEMM (+bias)
//   C[m, col] = emb_table[x[m]] . W[:, col] + b[col]
//   M tile = 128 rows = exactly one sequence's T steps (n = blockIdx.x)
//   blockIdx.z = direction; dir==1 stores rows time-reversed.
// 128x128x8 tile, 256 threads, 8x8 micro-tile, reg-prefetch double buffer.
// =====================================================================
__global__ __launch_bounds__(256) void proj_kernel(
    const int* __restrict__ x, const float* __restrict__ emb,
    const float* __restrict__ W_f, const float* __restrict__ b_f,
    const float* __restrict__ W_b, const float* __restrict__ b_b)
{
    __shared__ int   ids_s[128];
    __shared__ float As[2][8 * 128];   // [k][m]
    __shared__ float Bs[2][8 * 128];   // [k][col]

    const int tid = threadIdx.x;
    const int n   = blockIdx.x;        // sequence 0..255
    const int c0  = blockIdx.y * 128;  // gate-col tile
    const int dir = blockIdx.z;
    const float* __restrict__ W    = dir ? W_b : W_f;
    const float* __restrict__ bias = dir ? b_b : b_f;

    if (tid < 128) ids_s[tid] = x[n * TSEQ + tid];
    __syncthreads();

    const int tx = tid & 15, ty = tid >> 4;
    const int arow  = tid >> 1;            // 0..127
    const int ahalf = (tid & 1) * 4;       // k sub-offset 0/4
    const int brow  = tid >> 5;            // 0..7 (k)
    const int bcol  = (tid & 31) * 4;      // 0..124
    const int myid  = ids_s[arow];
    const float* arow_base = emb + (size_t)myid * EMBED + ahalf;

    float acc[8][8];
    #pragma unroll
    for (int r = 0; r < 8; r++)
        #pragma unroll
        for (int c = 0; c < 8; c++) acc[r][c] = 0.f;

    float4 av = *(const float4*)(arow_base);
    float4 bv = *(const float4*)(W + (size_t)brow * G4 + c0 + bcol);

    int p = 0;
    for (int k0 = 0; k0 < EMBED; k0 += 8) {
        As[p][(ahalf + 0) * 128 + arow] = av.x;
        As[p][(ahalf + 1) * 128 + arow] = av.y;
        As[p][(ahalf + 2) * 128 + arow] = av.z;
        As[p][(ahalf + 3) * 128 + arow] = av.w;
        *(float4*)&Bs[p][brow * 128 + bcol] = bv;
        __syncthreads();
        if (k0 + 8 < EMBED) {
            av = *(const float4*)(arow_base + k0 + 8);
            bv = *(const float4*)(W + (size_t)(k0 + 8 + brow) * G4 + c0 + bcol);
        }
        #pragma unroll
        for (int k = 0; k < 8; k++) {
            float a_[8], b_[8];
            *(float4*)&a_[0] = *(float4*)&As[p][k * 128 + ty * 8];
            *(float4*)&a_[4] = *(float4*)&As[p][k * 128 + ty * 8 + 4];
            *(float4*)&b_[0] = *(float4*)&Bs[p][k * 128 + tx * 8];
            *(float4*)&b_[4] = *(float4*)&Bs[p][k * 128 + tx * 8 + 4];
            #pragma unroll
            for (int r = 0; r < 8; r++)
                #pragma unroll
                for (int c = 0; c < 8; c++)
                    acc[r][c] = fmaf(a_[r], b_[c], acc[r][c]);
        }
        p ^= 1;
    }

    float bb[8];
    #pragma unroll
    for (int c = 0; c < 8; c++) bb[c] = bias[c0 + tx * 8 + c];

    #pragma unroll
    for (int r = 0; r < 8; r++) {
        int trow = ty * 8 + r;                       // token time within sequence
        int ts   = dir ? (TSEQ - 1 - trow) : trow;   // storage step (reversed for bwd)
        float* dst = &g_xW[dir][ts][n][c0 + tx * 8];
        float4 o0 = make_float4(acc[r][0] + bb[0], acc[r][1] + bb[1],
                                acc[r][2] + bb[2], acc[r][3] + bb[3]);
        float4 o1 = make_float4(acc[r][4] + bb[4], acc[r][5] + bb[5],
                                acc[r][6] + bb[6], acc[r][7] + bb[7]);
        *(float4*)(dst)     = o0;
        *(float4*)(dst + 4) = o1;
    }
}

// =====================================================================
// Kernel 2: one LSTM timestep, both directions (blockIdx.z).
// Block tile: 64 rows x 32 units (= 128 gate cols i/f/g/o remapped).
// Grid (4,16,2) = 128 blocks. h/c double buffered (pr -> pw) so blocks
// never read h that another block writes in the same launch.
// Shared (32 KB) is staging (2x(hs 4KB) + 2x(Us 8KB) = 24KB) during GEMM,
// then reused as the 64x128 z tile (32KB).
// =====================================================================
__global__ __launch_bounds__(256) void step_kernel(
    const int* __restrict__ x,
    const float* __restrict__ U_f, const float* __restrict__ U_b, int t)
{
    __shared__ float smem[8192];   // 32 KB

    const int dir  = blockIdx.z;
    const float* __restrict__ U = dir ? U_b : U_f;
    const int row0 = blockIdx.x * 64;
    const int u0   = blockIdx.y * 32;
    const int pr   = t & 1;        // read buffer
    const int pw   = pr ^ 1;       // write buffer
    const int tid  = threadIdx.x;
    const int tx = tid & 15, ty = tid >> 4;

    float acc[4][8];
    #pragma unroll
    for (int r = 0; r < 4; r++)
        #pragma unroll
        for (int c = 0; c < 8; c++) acc[r][c] = 0.f;

    if (t > 0) {
        const float* hsrc = &g_h[dir][pr][0][0];
        const int hr = tid >> 2;             // 0..63 row
        const int hk = (tid & 3) * 4;        // k sub-offset 0/4/8/12
        const int k0a = tid >> 5,        q0 = tid & 31;          // U load slot 0
        const int k1a = (tid + 256) >> 5, q1 = (tid + 256) & 31; // U load slot 1
        const int ucol0 = (q0 >> 3) * 512 + u0 + (q0 & 7) * 4;
        const int ucol1 = (q1 >> 3) * 512 + u0 + (q1 & 7) * 4;
        const int uoff0 = (q0 >> 3) * 32 + (q0 & 7) * 4;
        const int uoff1 = (q1 >> 3) * 32 + (q1 & 7) * 4;

        float4 hv  = *(const float4*)(hsrc + (size_t)(row0 + hr) * UNITS + hk);
        float4 uv0 = *(const float4*)(U + (size_t)k0a * G4 + ucol0);
        float4 uv1 = *(const float4*)(U + (size_t)k1a * G4 + ucol1);

        int p = 0;
        for (int k0 = 0; k0 < UNITS; k0 += 16) {
            float* hs = smem + p * 1024;
            float* us = smem + 2048 + p * 2048;
            hs[(hk + 0) * 64 + hr] = hv.x;
            hs[(hk + 1) * 64 + hr] = hv.y;
            hs[(hk + 2) * 64 + hr] = hv.z;
            hs[(hk + 3) * 64 + hr] = hv.w;
            *(float4*)&us[k0a * 128 + uoff0] = uv0;
            *(float4*)&us[k1a * 128 + uoff1] = uv1;
            __syncthreads();
            if (k0 + 16 < UNITS) {
                hv  = *(const float4*)(hsrc + (size_t)(row0 + hr) * UNITS + k0 + 16 + hk);
                uv0 = *(const float4*)(U + (size_t)(k0 + 16 + k0a) * G4 + ucol0);
                uv1 = *(const float4*)(U + (size_t)(k0 + 16 + k1a) * G4 + ucol1);
            }
            #pragma unroll
            for (int k = 0; k < 16; k++) {
                float a_[4], b_[8];
                *(float4*)&a_[0] = *(float4*)&hs[k * 64 + ty * 4];
                *(float4*)&b_[0] = *(float4*)&us[k * 128 + tx * 8];
                *(float4*)&b_[4] = *(float4*)&us[k * 128 + tx * 8 + 4];
                #pragma unroll
                for (int r = 0; r < 4; r++)
                    #pragma unroll
                    for (int c = 0; c < 8; c++)
                        acc[r][c] = fmaf(a_[r], b_[c], acc[r][c]);
            }
            p ^= 1;
        }
        __syncthreads();   // all reads of staging done before z-tile overwrite
    }

    // write z (= h@U contribution) tile to shared so threads can regroup gates
    float* zs = smem;
    #pragma unroll
    for (int r = 0; r < 4; r++) {
        *(float4*)&zs[(ty * 4 + r) * 128 + tx * 8]     = *(float4*)&acc[r][0];
        *(float4*)&zs[(ty * 4 + r) * 128 + tx * 8 + 4] = *(float4*)&acc[r][4];
    }
    __syncthreads();

    // elementwise gate update: 64 rows x 32 units = 2048 items, 8 per thread
    const float* xw = &g_xW[dir][t][0][0];
    const int tt = dir ? (TSEQ - 1 - t) : t;   // actual token index for mask
    #pragma unroll
    for (int i = 0; i < 8; i++) {
        int idx = tid + i * 256;
        int r = idx >> 5, u = idx & 31;
        int gr = row0 + r, gu = u0 + u;
        const float* xwr = xw + (size_t)gr * G4;
        float zi = zs[r * 128 + u]       + xwr[gu];
        float zf = zs[r * 128 + 32 + u]  + xwr[512 + gu];
        float zg = zs[r * 128 + 64 + u]  + xwr[1024 + gu];
        float zo = zs[r * 128 + 96 + u]  + xwr[1536 + gu];
        float ig = 1.f / (1.f + expf(-zi));
        float fg = 1.f / (1.f + expf(-zf));
        float gg = tanhf(zg);
        float og = 1.f / (1.f + expf(-zo));
        float cold = (t > 0) ? g_c[dir][pr][gr][gu] : 0.f;
        float hold = (t > 0) ? g_h[dir][pr][gr][gu] : 0.f;
        float cn = fg * cold + ig * gg;
        float hn = og * tanhf(cn);
        bool msk = x[gr * TSEQ + tt] != 0;
        // always write the next buffer (carry state when masked) -> no races,
        // deterministic across graph replays
        g_h[dir][pw][gr][gu] = msk ? hn : hold;
        g_c[dir][pw][gr][gu] = msk ? cn : cold;
    }
}

// =====================================================================
// Kernel 3: concat [h_fwd, h_bwd] -> out (B,S,1024)
// After t=127 (pr=1, pw=0) the final state lives in buffer 0.
// =====================================================================
__global__ void copy_out_kernel(float* __restrict__ out)
{
    int i = blockIdx.x * 256 + threadIdx.x;   // 0 .. 262143
    int n   = i >> 10;
    int u   = i & 1023;
    int dir = u >> 9;
    int uu  = u & 511;
    out[i] = g_h[dir][0][n][uu];
}

// =====================================================================
extern "C" void kernel_launch(void* const* d_in, const int* in_sizes, int n_in,
                              void* d_out, int out_size)
{
    (void)in_sizes; (void)n_in; (void)out_size;
    const int*   x    = (const int*)  d_in[0];
    const float* emb  = (const float*)d_in[1];
    const float* W_f  = (const float*)d_in[2];
    const float* U_f  = (const float*)d_in[3];
    const float* b_f  = (const float*)d_in[4];
    const float* W_b  = (const float*)d_in[5];
    const float* U_b  = (const float*)d_in[6];
    const float* b_b  = (const float*)d_in[7];
    float* out = (float*)d_out;

    dim3 pgrid(NSEQ, G4 / 128, 2);        // (256, 16, 2) both directions
    proj_kernel<<<pgrid, 256>>>(x, emb, W_f, b_f, W_b, b_b);

    dim3 sgrid(NSEQ / 64, UNITS / 32, 2); // (4, 16, 2)
    for (int t = 0; t < TSEQ; t++)
        step_kernel<<<sgrid, 256>>>(x, U_f, U_b, t);

    copy_out_kernel<<<(NSEQ * 1024) / 256, 256>>>(out);
}

// round 6
// speedup vs baseline: 2.5223x; 2.5223x over previous
#include <cuda_runtime.h>
#include <cuda_bf16.h>
#include <math.h>
#include <stdint.h>

#define NSEQ  256     // B*S
#define TSEQ  128
#define EMBED 512
#define UNITS 512
#define G4    2048    // 4*UNITS
#define KDIM  512
#define KC    64      // k-chunk (bf16 elems) = 128B row
#define NCHUNK 8
#define MTILE 64      // rows per step CTA
#define NTILE 128     // 32 units * 4 gates (permuted cols)

// ---------------- scratch (__device__ globals, allocation-free) ----------------
__device__ __align__(16) float g_xW[2][TSEQ][NSEQ][G4];               // 512 MB
// h as bf16 hi/lo split, double buffered: [dir][buf][split][n][k]
__device__ __align__(16) __nv_bfloat16 g_hbf[2][2][2][NSEQ][UNITS];   // 2 MB
// U as bf16 hi/lo, gate-permuted cols n' = 4u+g: [dir][split][n'][k]
__device__ __align__(16) __nv_bfloat16 g_Ubf[2][2][G4][KDIM];         // 16 MB
__device__ __align__(16) float g_c[2][2][NSEQ][UNITS];                // 2 MB

// ---------------- helpers ----------------
__device__ __forceinline__ uint32_t smem_u32(const void* p) {
    uint32_t a;
    asm("{ .reg .u64 t; cvta.to.shared.u64 t, %1; cvt.u32.u64 %0, t; }" : "=r"(a) : "l"(p));
    return a;
}
// XOR swizzle for 128B rows: 16B granules, conflict-free ldmatrix
#define SWZ(r, kb) (((r) * 128) + ((kb) ^ (((r) & 7) << 4)))

#define LDSM_X4(r0, r1, r2, r3, addr) \
    asm volatile("ldmatrix.sync.aligned.m8n8.x4.shared.b16 {%0,%1,%2,%3}, [%4];" \
        : "=r"(r0), "=r"(r1), "=r"(r2), "=r"(r3) : "r"(addr))

#define MMA16816(d, a, b0, b1) \
    asm volatile("mma.sync.aligned.m16n8k16.row.col.f32.bf16.bf16.f32 " \
        "{%0,%1,%2,%3}, {%4,%5,%6,%7}, {%8,%9}, {%0,%1,%2,%3};" \
        : "+f"((d)[0]), "+f"((d)[1]), "+f"((d)[2]), "+f"((d)[3]) \
        : "r"((a)[0]), "r"((a)[1]), "r"((a)[2]), "r"((a)[3]), "r"(b0), "r"(b1))

// step-kernel smem layout (48 KB static, z-tile overlays staging)
#define A_HI 0
#define A_LO 8192
#define B_HI 16384
#define B_LO 32768

// =====================================================================
// Kernel 1: fused embedding-gather + input projection GEMM (+bias), fp32.
// (unchanged from passing R4 kernel — at fp32 FFMA roofline)
// =====================================================================
__global__ __launch_bounds__(256) void proj_kernel(
    const int* __restrict__ x, const float* __restrict__ emb,
    const float* __restrict__ W_f, const float* __restrict__ b_f,
    const float* __restrict__ W_b, const float* __restrict__ b_b)
{
    __shared__ int   ids_s[128];
    __shared__ float As[2][8 * 128];
    __shared__ float Bs[2][8 * 128];

    const int tid = threadIdx.x;
    const int n   = blockIdx.x;
    const int c0  = blockIdx.y * 128;
    const int dir = blockIdx.z;
    const float* __restrict__ W    = dir ? W_b : W_f;
    const float* __restrict__ bias = dir ? b_b : b_f;

    if (tid < 128) ids_s[tid] = x[n * TSEQ + tid];
    __syncthreads();

    const int tx = tid & 15, ty = tid >> 4;
    const int arow  = tid >> 1;
    const int ahalf = (tid & 1) * 4;
    const int brow  = tid >> 5;
    const int bcol  = (tid & 31) * 4;
    const int myid  = ids_s[arow];
    const float* arow_base = emb + (size_t)myid * EMBED + ahalf;

    float acc[8][8];
    #pragma unroll
    for (int r = 0; r < 8; r++)
        #pragma unroll
        for (int c = 0; c < 8; c++) acc[r][c] = 0.f;

    float4 av = *(const float4*)(arow_base);
    float4 bv = *(const float4*)(W + (size_t)brow * G4 + c0 + bcol);

    int p = 0;
    for (int k0 = 0; k0 < EMBED; k0 += 8) {
        As[p][(ahalf + 0) * 128 + arow] = av.x;
        As[p][(ahalf + 1) * 128 + arow] = av.y;
        As[p][(ahalf + 2) * 128 + arow] = av.z;
        As[p][(ahalf + 3) * 128 + arow] = av.w;
        *(float4*)&Bs[p][brow * 128 + bcol] = bv;
        __syncthreads();
        if (k0 + 8 < EMBED) {
            av = *(const float4*)(arow_base + k0 + 8);
            bv = *(const float4*)(W + (size_t)(k0 + 8 + brow) * G4 + c0 + bcol);
        }
        #pragma unroll
        for (int k = 0; k < 8; k++) {
            float a_[8], b_[8];
            *(float4*)&a_[0] = *(float4*)&As[p][k * 128 + ty * 8];
            *(float4*)&a_[4] = *(float4*)&As[p][k * 128 + ty * 8 + 4];
            *(float4*)&b_[0] = *(float4*)&Bs[p][k * 128 + tx * 8];
            *(float4*)&b_[4] = *(float4*)&Bs[p][k * 128 + tx * 8 + 4];
            #pragma unroll
            for (int r = 0; r < 8; r++)
                #pragma unroll
                for (int c = 0; c < 8; c++)
                    acc[r][c] = fmaf(a_[r], b_[c], acc[r][c]);
        }
        p ^= 1;
    }

    float bb[8];
    #pragma unroll
    for (int c = 0; c < 8; c++) bb[c] = bias[c0 + tx * 8 + c];

    #pragma unroll
    for (int r = 0; r < 8; r++) {
        int trow = ty * 8 + r;
        int ts   = dir ? (TSEQ - 1 - trow) : trow;
        float* dst = &g_xW[dir][ts][n][c0 + tx * 8];
        float4 o0 = make_float4(acc[r][0] + bb[0], acc[r][1] + bb[1],
                                acc[r][2] + bb[2], acc[r][3] + bb[3]);
        float4 o1 = make_float4(acc[r][4] + bb[4], acc[r][5] + bb[5],
                                acc[r][6] + bb[6], acc[r][7] + bb[7]);
        *(float4*)(dst)     = o0;
        *(float4*)(dst + 4) = o1;
    }
}

// =====================================================================
// Kernel 1b: U (fp32, col = g*512+u) -> bf16 hi/lo, permuted col' = 4u+g,
// layout [dir][split][n'][k] (k contiguous: B operand rows).
// =====================================================================
__global__ void conv_u_kernel(const float* __restrict__ U_f,
                              const float* __restrict__ U_b)
{
    const int c   = blockIdx.x;           // original col 0..2047
    const int dir = blockIdx.y;
    const float* __restrict__ U = dir ? U_b : U_f;
    const int g = c >> 9, u = c & 511;
    const int np = 4 * u + g;
    for (int k = threadIdx.x; k < KDIM; k += blockDim.x) {
        float v = U[(size_t)k * G4 + c];
        __nv_bfloat16 hi = __float2bfloat16(v);
        __nv_bfloat16 lo = __float2bfloat16(v - __bfloat162float(hi));
        g_Ubf[dir][0][np][k] = hi;
        g_Ubf[dir][1][np][k] = lo;
    }
}

// =====================================================================
// Kernel 2: one LSTM timestep via mma.sync bf16x3 (hi*hi + hi*lo + lo*hi).
// Grid (4, 16, 2): M=64 rows, 32 units (N=128 permuted gate cols), dir.
// 256 threads = 8 warps, warp tile 16x64. K=512 in 8 chunks of 64.
// z written to smem (overlay), then R4-style fp32 gate epilogue.
// =====================================================================
__global__ __launch_bounds__(256) void step_kernel(const int* __restrict__ x, int t)
{
    __shared__ char smem[49152];   // A hi/lo 16KB + B hi/lo 32KB; z overlays
    const uint32_t sb = smem_u32(smem);

    const int tid  = threadIdx.x;
    const int lane = tid & 31;
    const int wid  = tid >> 5;
    const int dir  = blockIdx.z;
    const int m0   = blockIdx.x * MTILE;
    const int ub0  = blockIdx.y * 32;         // global unit base
    const int np0  = blockIdx.y * NTILE;      // permuted col base = 4*ub0
    const int pr   = t & 1, pw = pr ^ 1;

    float* zs = (float*)smem;                 // 64 x 128 fp32 (32 KB overlay)

    if (t > 0) {
        const int wm = (wid >> 1) * 16;       // warp row base 0/16/32/48
        const int wn = (wid & 1)  * 64;       // warp col base 0/64

        float acc[8][4];
        #pragma unroll
        for (int nb = 0; nb < 8; nb++)
            #pragma unroll
            for (int j = 0; j < 4; j++) acc[nb][j] = 0.f;

        // per-thread ldmatrix source coords (within tile, before swizzle)
        const int a_row = wm + (lane & 15);
        const int a_kb  = (lane >> 4) * 16;
        const int b_rowo = (lane & 7) + (lane >> 4) * 8;
        const int b_kb   = ((lane >> 3) & 1) * 16;

        for (int kc = 0; kc < NCHUNK; kc++) {
            // ---- stage A (h) hi/lo: 64 rows x 128B, swizzled ----
            #pragma unroll
            for (int s = 0; s < 2; s++) {
                const int off = s ? A_LO : A_HI;
                #pragma unroll
                for (int it = 0; it < 2; it++) {
                    int i = tid + it * 256;          // 512 chunks of 16B
                    int r = i >> 3, cc = (i & 7) * 16;
                    uint4 v = *(const uint4*)((const char*)&g_hbf[dir][pr][s][m0 + r][kc * KC] + cc);
                    *(uint4*)(smem + off + SWZ(r, cc)) = v;
                }
            }
            // ---- stage B (U) hi/lo: 128 rows x 128B, swizzled ----
            #pragma unroll
            for (int s = 0; s < 2; s++) {
                const int off = s ? B_LO : B_HI;
                #pragma unroll
                for (int it = 0; it < 4; it++) {
                    int i = tid + it * 256;          // 1024 chunks of 16B
                    int r = i >> 3, cc = (i & 7) * 16;
                    uint4 v = *(const uint4*)((const char*)&g_Ubf[dir][s][np0 + r][kc * KC] + cc);
                    *(uint4*)(smem + off + SWZ(r, cc)) = v;
                }
            }
            __syncthreads();

            // ---- 3 split passes: (Ahi,Bhi), (Ahi,Blo), (Alo,Bhi) ----
            #pragma unroll
            for (int s = 0; s < 3; s++) {
                const uint32_t abase = sb + ((s == 2) ? A_LO : A_HI);
                const uint32_t bbase = sb + ((s == 1) ? B_LO : B_HI);
                #pragma unroll
                for (int ks = 0; ks < 4; ks++) {     // k16 slices in chunk
                    uint32_t a[4];
                    LDSM_X4(a[0], a[1], a[2], a[3],
                            abase + SWZ(a_row, ks * 32 + a_kb));
                    uint32_t b[16];
                    #pragma unroll
                    for (int nb4 = 0; nb4 < 4; nb4++) {  // each covers n16
                        int row = wn + nb4 * 16 + b_rowo;
                        LDSM_X4(b[nb4 * 4 + 0], b[nb4 * 4 + 1],
                                b[nb4 * 4 + 2], b[nb4 * 4 + 3],
                                bbase + SWZ(row, ks * 32 + b_kb));
                    }
                    #pragma unroll
                    for (int nb = 0; nb < 8; nb++) {
                        const int bi = (nb >> 1) * 4 + (nb & 1) * 2;
                        MMA16816(acc[nb], a, b[bi], b[bi + 1]);
                    }
                }
            }
            __syncthreads();   // staging reuse next chunk (and z overlay after)
        }

        // ---- write z tile to smem (overlay) ----
        const int zr = wm + (lane >> 2);
        const int zc0 = wn + (lane & 3) * 2;
        #pragma unroll
        for (int nb = 0; nb < 8; nb++) {
            int zc = zc0 + nb * 8;
            *(float2*)&zs[zr * 128 + zc]       = make_float2(acc[nb][0], acc[nb][1]);
            *(float2*)&zs[(zr + 8) * 128 + zc] = make_float2(acc[nb][2], acc[nb][3]);
        }
        __syncthreads();
    } else {
        #pragma unroll
        for (int i = 0; i < 32; i++) zs[tid + i * 256] = 0.f;
        __syncthreads();
    }

    // ---------------- epilogue: 64 rows x 32 units, 8 items/thread ----------------
    const float* xw = &g_xW[dir][t][0][0];
    const int tt = dir ? (TSEQ - 1 - t) : t;
    #pragma unroll
    for (int i = 0; i < 8; i++) {
        int idx = tid + i * 256;
        int r = idx >> 5, ul = idx & 31;
        int gr = m0 + r, gu = ub0 + ul;
        const float* xwr = xw + (size_t)gr * G4;
        float zi = zs[r * 128 + 4 * ul + 0] + xwr[gu];
        float zf = zs[r * 128 + 4 * ul + 1] + xwr[512 + gu];
        float zg = zs[r * 128 + 4 * ul + 2] + xwr[1024 + gu];
        float zo = zs[r * 128 + 4 * ul + 3] + xwr[1536 + gu];
        float ig = 1.f / (1.f + expf(-zi));
        float fg = 1.f / (1.f + expf(-zf));
        float gg = tanhf(zg);
        float og = 1.f / (1.f + expf(-zo));
        float cold = (t > 0) ? g_c[dir][pr][gr][gu] : 0.f;
        float cn = fg * cold + ig * gg;
        float hn = og * tanhf(cn);
        bool msk = x[gr * TSEQ + tt] != 0;

        __nv_bfloat16 oh = __float2bfloat16(0.f), ol = oh;
        if (t > 0) { oh = g_hbf[dir][pr][0][gr][gu]; ol = g_hbf[dir][pr][1][gr][gu]; }
        __nv_bfloat16 nh, nl;
        if (msk) {
            nh = __float2bfloat16(hn);
            nl = __float2bfloat16(hn - __bfloat162float(nh));
        } else { nh = oh; nl = ol; }
        g_c[dir][pw][gr][gu] = msk ? cn : cold;
        g_hbf[dir][pw][0][gr][gu] = nh;
        g_hbf[dir][pw][1][gr][gu] = nl;
    }
}

// =====================================================================
// Kernel 3: concat [h_fwd, h_bwd] -> out fp32. Final state in buf 0
// (t=127: pw=0). h = hi + lo.
// =====================================================================
__global__ void copy_out_kernel(float* __restrict__ out)
{
    int i = blockIdx.x * 256 + threadIdx.x;   // 0 .. 262143
    int n   = i >> 10;
    int u   = i & 1023;
    int dir = u >> 9;
    int uu  = u & 511;
    out[i] = __bfloat162float(g_hbf[dir][0][0][n][uu]) +
             __bfloat162float(g_hbf[dir][0][1][n][uu]);
}

// =====================================================================
extern "C" void kernel_launch(void* const* d_in, const int* in_sizes, int n_in,
                              void* d_out, int out_size)
{
    (void)in_sizes; (void)n_in; (void)out_size;
    const int*   x    = (const int*)  d_in[0];
    const float* emb  = (const float*)d_in[1];
    const float* W_f  = (const float*)d_in[2];
    const float* U_f  = (const float*)d_in[3];
    const float* b_f  = (const float*)d_in[4];
    const float* W_b  = (const float*)d_in[5];
    const float* U_b  = (const float*)d_in[6];
    const float* b_b  = (const float*)d_in[7];
    float* out = (float*)d_out;

    dim3 pgrid(NSEQ, G4 / 128, 2);
    proj_kernel<<<pgrid, 256>>>(x, emb, W_f, b_f, W_b, b_b);

    conv_u_kernel<<<dim3(G4, 2), 128>>>(U_f, U_b);

    dim3 sgrid(NSEQ / MTILE, G4 / NTILE, 2);   // (4, 16, 2)
    for (int t = 0; t < TSEQ; t++)
        step_kernel<<<sgrid, 256>>>(x, t);

    copy_out_kernel<<<(NSEQ * 1024) / 256, 256>>>(out);
}

// round 7
// speedup vs baseline: 3.4703x; 1.3758x over previous
#include <cuda_runtime.h>
#include <cuda_bf16.h>
#include <math.h>
#include <stdint.h>

#define NSEQ  256     // B*S
#define TSEQ  128
#define EMBED 512
#define UNITS 512
#define G4    2048    // 4*UNITS
#define KDIM  512
#define KC    64      // k-chunk (bf16 elems) = 128B row
#define NCHUNK 8
#define MTILE 64      // rows per step CTA
#define NTILE 128     // 32 units * 4 gates (permuted cols)

// ---------------- scratch (__device__ globals, allocation-free) ----------------
__device__ __align__(16) float g_xW[2][TSEQ][NSEQ][G4];               // 512 MB
__device__ __align__(16) __nv_bfloat16 g_hbf[2][2][2][NSEQ][UNITS];   // h hi/lo, dbl-buf
__device__ __align__(16) __nv_bfloat16 g_Ubf[2][2][G4][KDIM];         // U hi/lo, permuted
__device__ __align__(16) __nv_bfloat16 g_Wbf[2][2][G4][KDIM];         // W hi/lo, natural
__device__ __align__(16) float g_c[2][2][NSEQ][UNITS];

// ---------------- helpers ----------------
__device__ __forceinline__ uint32_t smem_u32(const void* p) {
    uint32_t a;
    asm("{ .reg .u64 t; cvta.to.shared.u64 t, %1; cvt.u32.u64 %0, t; }" : "=r"(a) : "l"(p));
    return a;
}
#define SWZ(r, kb) (((r) * 128) + ((kb) ^ (((r) & 7) << 4)))

#define LDSM_X4(r0, r1, r2, r3, addr) \
    asm volatile("ldmatrix.sync.aligned.m8n8.x4.shared.b16 {%0,%1,%2,%3}, [%4];" \
        : "=r"(r0), "=r"(r1), "=r"(r2), "=r"(r3) : "r"(addr))

#define MMA16816(d, a, b0, b1) \
    asm volatile("mma.sync.aligned.m16n8k16.row.col.f32.bf16.bf16.f32 " \
        "{%0,%1,%2,%3}, {%4,%5,%6,%7}, {%8,%9}, {%0,%1,%2,%3};" \
        : "+f"((d)[0]), "+f"((d)[1]), "+f"((d)[2]), "+f"((d)[3]) \
        : "r"((a)[0]), "r"((a)[1]), "r"((a)[2]), "r"((a)[3]), "r"(b0), "r"(b1))

#define CP_A16(dst, src) \
    asm volatile("cp.async.cg.shared.global [%0], [%1], 16;" \
        :: "r"(dst), "l"(__cvta_generic_to_global(src)) : "memory")
#define CP_COMMIT() asm volatile("cp.async.commit_group;" ::: "memory")
#define CP_WAIT(n)  asm volatile("cp.async.wait_group %0;" :: "n"(n) : "memory")

__device__ __forceinline__ uint32_t pkraw(__nv_bfloat16 a, __nv_bfloat16 b) {
    __nv_bfloat162 t = __halves2bfloat162(a, b);
    return *reinterpret_cast<uint32_t*>(&t);
}

// step-kernel stage layout (per 48KB stage buffer; two buffers)
#define A_HI 0
#define A_LO 8192
#define B_HI 16384
#define B_LO 32768
#define STAGE_SZ 49152
#define STEP_SMEM (2 * STAGE_SZ)

// proj stage layout (single 64KB buffer)
#define PA_HI 0
#define PA_LO 16384
#define PB_HI 32768
#define PB_LO 49152
#define PROJ_SMEM 65536

// =====================================================================
// conv kernels: fp32 matrices -> bf16 hi/lo split.
// U gets gate-permuted cols (n' = 4u+g); W keeps natural cols.
// =====================================================================
__global__ void conv_u_kernel(const float* __restrict__ U_f,
                              const float* __restrict__ U_b)
{
    const int c   = blockIdx.x;
    const int dir = blockIdx.y;
    const float* __restrict__ U = dir ? U_b : U_f;
    const int g = c >> 9, u = c & 511;
    const int np = 4 * u + g;
    for (int k = threadIdx.x; k < KDIM; k += blockDim.x) {
        float v = U[(size_t)k * G4 + c];
        __nv_bfloat16 hi = __float2bfloat16(v);
        g_Ubf[dir][0][np][k] = hi;
        g_Ubf[dir][1][np][k] = __float2bfloat16(v - __bfloat162float(hi));
    }
}

__global__ void conv_w_kernel(const float* __restrict__ W_f,
                              const float* __restrict__ W_b)
{
    const int c   = blockIdx.x;
    const int dir = blockIdx.y;
    const float* __restrict__ W = dir ? W_b : W_f;
    for (int k = threadIdx.x; k < KDIM; k += blockDim.x) {
        float v = W[(size_t)k * G4 + c];
        __nv_bfloat16 hi = __float2bfloat16(v);
        g_Wbf[dir][0][c][k] = hi;
        g_Wbf[dir][1][c][k] = __float2bfloat16(v - __bfloat162float(hi));
    }
}

// =====================================================================
// Kernel 1: embedding-gather + input projection via mma.sync bf16x3.
// Grid (256, 16, 2): M=128 (one sequence's tokens), N=128 cols, dir.
// 8 warps, warp tile 32x64. A (emb rows) converted to hi/lo on the fly.
// =====================================================================
__global__ __launch_bounds__(256) void proj_mma_kernel(
    const int* __restrict__ x, const float* __restrict__ emb,
    const float* __restrict__ b_f, const float* __restrict__ b_b)
{
    extern __shared__ char psm[];
    __shared__ int ids_s[128];
    const uint32_t sb = smem_u32(psm);

    const int tid  = threadIdx.x;
    const int lane = tid & 31;
    const int wid  = tid >> 5;
    const int n    = blockIdx.x;
    const int c0   = blockIdx.y * 128;
    const int dir  = blockIdx.z;
    const float* __restrict__ bias = dir ? b_b : b_f;

    if (tid < 128) ids_s[tid] = x[n * TSEQ + tid];
    __syncthreads();

    const int wm = (wid & 3) * 32;
    const int wn = (wid >> 2) * 64;

    float acc[2][8][4];
    #pragma unroll
    for (int h = 0; h < 2; h++)
        #pragma unroll
        for (int nb = 0; nb < 8; nb++)
            #pragma unroll
            for (int j = 0; j < 4; j++) acc[h][nb][j] = 0.f;

    const int a_row  = lane & 15;
    const int a_kb   = (lane >> 4) * 16;
    const int b_rowo = (lane & 7) + (lane >> 4) * 8;
    const int b_kb   = ((lane >> 3) & 1) * 16;

    for (int kc = 0; kc < NCHUNK; kc++) {
        // ---- stage A: gather emb rows (fp32) -> hi/lo bf16, swizzled ----
        #pragma unroll
        for (int it = 0; it < 4; it++) {
            int i = tid + it * 256;            // 1024 granules of 8 elems
            int r = i >> 3, g8 = i & 7;
            const float* src = emb + (size_t)ids_s[r] * EMBED + kc * KC + g8 * 8;
            float4 f0 = *(const float4*)src;
            float4 f1 = *(const float4*)(src + 4);
            __nv_bfloat16 h0 = __float2bfloat16(f0.x), h1 = __float2bfloat16(f0.y);
            __nv_bfloat16 h2 = __float2bfloat16(f0.z), h3 = __float2bfloat16(f0.w);
            __nv_bfloat16 h4 = __float2bfloat16(f1.x), h5 = __float2bfloat16(f1.y);
            __nv_bfloat16 h6 = __float2bfloat16(f1.z), h7 = __float2bfloat16(f1.w);
            uint4 hv = make_uint4(pkraw(h0, h1), pkraw(h2, h3), pkraw(h4, h5), pkraw(h6, h7));
            uint4 lv = make_uint4(
                pkraw(__float2bfloat16(f0.x - __bfloat162float(h0)),
                      __float2bfloat16(f0.y - __bfloat162float(h1))),
                pkraw(__float2bfloat16(f0.z - __bfloat162float(h2)),
                      __float2bfloat16(f0.w - __bfloat162float(h3))),
                pkraw(__float2bfloat16(f1.x - __bfloat162float(h4)),
                      __float2bfloat16(f1.y - __bfloat162float(h5))),
                pkraw(__float2bfloat16(f1.z - __bfloat162float(h6)),
                      __float2bfloat16(f1.w - __bfloat162float(h7))));
            *(uint4*)(psm + PA_HI + SWZ(r, g8 * 16)) = hv;
            *(uint4*)(psm + PA_LO + SWZ(r, g8 * 16)) = lv;
        }
        // ---- stage B: W hi/lo (pre-converted), swizzled ----
        #pragma unroll
        for (int s = 0; s < 2; s++) {
            const int off = s ? PB_LO : PB_HI;
            #pragma unroll
            for (int it = 0; it < 4; it++) {
                int i = tid + it * 256;
                int r = i >> 3, cc = (i & 7) * 16;
                uint4 v = *(const uint4*)((const char*)&g_Wbf[dir][s][c0 + r][kc * KC] + cc);
                *(uint4*)(psm + off + SWZ(r, cc)) = v;
            }
        }
        __syncthreads();

        #pragma unroll
        for (int s = 0; s < 3; s++) {
            const uint32_t abase = sb + ((s == 2) ? PA_LO : PA_HI);
            const uint32_t bbase = sb + ((s == 1) ? PB_LO : PB_HI);
            #pragma unroll
            for (int ks = 0; ks < 4; ks++) {
                uint32_t a0[4], a1[4];
                LDSM_X4(a0[0], a0[1], a0[2], a0[3],
                        abase + SWZ(wm + a_row, ks * 32 + a_kb));
                LDSM_X4(a1[0], a1[1], a1[2], a1[3],
                        abase + SWZ(wm + 16 + a_row, ks * 32 + a_kb));
                uint32_t b[16];
                #pragma unroll
                for (int nb4 = 0; nb4 < 4; nb4++) {
                    int row = wn + nb4 * 16 + b_rowo;
                    LDSM_X4(b[nb4 * 4 + 0], b[nb4 * 4 + 1],
                            b[nb4 * 4 + 2], b[nb4 * 4 + 3],
                            bbase + SWZ(row, ks * 32 + b_kb));
                }
                #pragma unroll
                for (int nb = 0; nb < 8; nb++) {
                    const int bi = (nb >> 1) * 4 + (nb & 1) * 2;
                    MMA16816(acc[0][nb], a0, b[bi], b[bi + 1]);
                    MMA16816(acc[1][nb], a1, b[bi], b[bi + 1]);
                }
            }
        }
        __syncthreads();
    }

    // ---- epilogue: bias + store to g_xW (dir-reversed rows) ----
    #pragma unroll
    for (int h = 0; h < 2; h++) {
        #pragma unroll
        for (int nb = 0; nb < 8; nb++) {
            int col = wn + nb * 8 + (lane & 3) * 2;
            float bi0 = bias[c0 + col], bi1 = bias[c0 + col + 1];
            int r0 = wm + h * 16 + (lane >> 2);
            int r1 = r0 + 8;
            int ts0 = dir ? (TSEQ - 1 - r0) : r0;
            int ts1 = dir ? (TSEQ - 1 - r1) : r1;
            *(float2*)&g_xW[dir][ts0][n][c0 + col] =
                make_float2(acc[h][nb][0] + bi0, acc[h][nb][1] + bi1);
            *(float2*)&g_xW[dir][ts1][n][c0 + col] =
                make_float2(acc[h][nb][2] + bi0, acc[h][nb][3] + bi1);
        }
    }
}

// =====================================================================
// Kernel 2: one LSTM timestep via mma.sync bf16x3, cp.async double-buffered
// K-chunk pipeline. Grid (4, 16, 2): M=64, 32 units (N=128), dir.
// 8 warps, warp tile 16x64.
// =====================================================================
__global__ __launch_bounds__(256) void step_kernel(const int* __restrict__ x, int t)
{
    extern __shared__ char smem[];
    const uint32_t sb = smem_u32(smem);

    const int tid  = threadIdx.x;
    const int lane = tid & 31;
    const int wid  = tid >> 5;
    const int dir  = blockIdx.z;
    const int m0   = blockIdx.x * MTILE;
    const int ub0  = blockIdx.y * 32;
    const int np0  = blockIdx.y * NTILE;
    const int pr   = t & 1, pw = pr ^ 1;

    float* zs = (float*)smem;   // overlays stage buffer 0 (32 KB)

    if (t > 0) {
        const int wm = (wid >> 1) * 16;
        const int wn = (wid & 1)  * 64;

        float acc[8][4];
        #pragma unroll
        for (int nb = 0; nb < 8; nb++)
            #pragma unroll
            for (int j = 0; j < 4; j++) acc[nb][j] = 0.f;

        const int a_row  = wm + (lane & 15);
        const int a_kb   = (lane >> 4) * 16;
        const int b_rowo = (lane & 7) + (lane >> 4) * 8;
        const int b_kb   = ((lane >> 3) & 1) * 16;

        // per-thread copy coords
        const int ar = tid >> 3;            // A: rows 0..31 (x2 its -> 64)
        const int acc16 = (tid & 7) * 16;
        const int br = tid >> 3;            // B: rows (x4 its -> 128)
        const int bcc16 = (tid & 7) * 16;

        // ---- issue chunk 0 ----
        {
            const int sbase = 0;
            #pragma unroll
            for (int s = 0; s < 2; s++) {
                const int off = sbase + (s ? A_LO : A_HI);
                #pragma unroll
                for (int it = 0; it < 2; it++) {
                    int r = ar + it * 32;
                    CP_A16(sb + off + SWZ(r, acc16),
                           (const char*)&g_hbf[dir][pr][s][m0 + r][0] + acc16);
                }
            }
            #pragma unroll
            for (int s = 0; s < 2; s++) {
                const int off = sbase + (s ? B_LO : B_HI);
                #pragma unroll
                for (int it = 0; it < 4; it++) {
                    int r = br + it * 32;
                    CP_A16(sb + off + SWZ(r, bcc16),
                           (const char*)&g_Ubf[dir][s][np0 + r][0] + bcc16);
                }
            }
            CP_COMMIT();
        }

        for (int kc = 0; kc < NCHUNK; kc++) {
            if (kc + 1 < NCHUNK) {
                const int sbase = ((kc + 1) & 1) * STAGE_SZ;
                const int kb = (kc + 1) * KC;
                #pragma unroll
                for (int s = 0; s < 2; s++) {
                    const int off = sbase + (s ? A_LO : A_HI);
                    #pragma unroll
                    for (int it = 0; it < 2; it++) {
                        int r = ar + it * 32;
                        CP_A16(sb + off + SWZ(r, acc16),
                               (const char*)&g_hbf[dir][pr][s][m0 + r][kb] + acc16);
                    }
                }
                #pragma unroll
                for (int s = 0; s < 2; s++) {
                    const int off = sbase + (s ? B_LO : B_HI);
                    #pragma unroll
                    for (int it = 0; it < 4; it++) {
                        int r = br + it * 32;
                        CP_A16(sb + off + SWZ(r, bcc16),
                               (const char*)&g_Ubf[dir][s][np0 + r][kb] + bcc16);
                    }
                }
                CP_COMMIT();
                CP_WAIT(1);
            } else {
                CP_WAIT(0);
            }
            __syncthreads();

            const uint32_t stg = sb + (kc & 1) * STAGE_SZ;
            #pragma unroll
            for (int s = 0; s < 3; s++) {
                const uint32_t abase = stg + ((s == 2) ? A_LO : A_HI);
                const uint32_t bbase = stg + ((s == 1) ? B_LO : B_HI);
                #pragma unroll
                for (int ks = 0; ks < 4; ks++) {
                    uint32_t a[4];
                    LDSM_X4(a[0], a[1], a[2], a[3],
                            abase + SWZ(a_row, ks * 32 + a_kb));
                    uint32_t b[16];
                    #pragma unroll
                    for (int nb4 = 0; nb4 < 4; nb4++) {
                        int row = wn + nb4 * 16 + b_rowo;
                        LDSM_X4(b[nb4 * 4 + 0], b[nb4 * 4 + 1],
                                b[nb4 * 4 + 2], b[nb4 * 4 + 3],
                                bbase + SWZ(row, ks * 32 + b_kb));
                    }
                    #pragma unroll
                    for (int nb = 0; nb < 8; nb++) {
                        const int bi = (nb >> 1) * 4 + (nb & 1) * 2;
                        MMA16816(acc[nb], a, b[bi], b[bi + 1]);
                    }
                }
            }
            if (kc + 1 < NCHUNK) __syncthreads();  // protect buf reuse
        }

        // ---- write z tile to smem (overlays stage 0) ----
        const int zr  = wm + (lane >> 2);
        const int zc0 = wn + (lane & 3) * 2;
        #pragma unroll
        for (int nb = 0; nb < 8; nb++) {
            int zc = zc0 + nb * 8;
            *(float2*)&zs[zr * 128 + zc]       = make_float2(acc[nb][0], acc[nb][1]);
            *(float2*)&zs[(zr + 8) * 128 + zc] = make_float2(acc[nb][2], acc[nb][3]);
        }
        __syncthreads();
    } else {
        #pragma unroll
        for (int i = 0; i < 32; i++) zs[tid + i * 256] = 0.f;
        __syncthreads();
    }

    // ---------------- gate epilogue: 64 rows x 32 units ----------------
    const float* xw = &g_xW[dir][t][0][0];
    const int tt = dir ? (TSEQ - 1 - t) : t;
    #pragma unroll
    for (int i = 0; i < 8; i++) {
        int idx = tid + i * 256;
        int r = idx >> 5, ul = idx & 31;
        int gr = m0 + r, gu = ub0 + ul;
        const float* xwr = xw + (size_t)gr * G4;
        float zi = zs[r * 128 + 4 * ul + 0] + xwr[gu];
        float zf = zs[r * 128 + 4 * ul + 1] + xwr[512 + gu];
        float zg = zs[r * 128 + 4 * ul + 2] + xwr[1024 + gu];
        float zo = zs[r * 128 + 4 * ul + 3] + xwr[1536 + gu];
        float ig = 1.f / (1.f + expf(-zi));
        float fg = 1.f / (1.f + expf(-zf));
        float gg = tanhf(zg);
        float og = 1.f / (1.f + expf(-zo));
        float cold = (t > 0) ? g_c[dir][pr][gr][gu] : 0.f;
        float cn = fg * cold + ig * gg;
        float hn = og * tanhf(cn);
        bool msk = x[gr * TSEQ + tt] != 0;

        __nv_bfloat16 oh = __float2bfloat16(0.f), ol = oh;
        if (t > 0) { oh = g_hbf[dir][pr][0][gr][gu]; ol = g_hbf[dir][pr][1][gr][gu]; }
        __nv_bfloat16 nh, nl;
        if (msk) {
            nh = __float2bfloat16(hn);
            nl = __float2bfloat16(hn - __bfloat162float(nh));
        } else { nh = oh; nl = ol; }
        g_c[dir][pw][gr][gu] = msk ? cn : cold;
        g_hbf[dir][pw][0][gr][gu] = nh;
        g_hbf[dir][pw][1][gr][gu] = nl;
    }
}

// =====================================================================
// Kernel 3: concat [h_fwd, h_bwd] -> out fp32 (final state in buf 0).
// =====================================================================
__global__ void copy_out_kernel(float* __restrict__ out)
{
    int i = blockIdx.x * 256 + threadIdx.x;
    int n   = i >> 10;
    int u   = i & 1023;
    int dir = u >> 9;
    int uu  = u & 511;
    out[i] = __bfloat162float(g_hbf[dir][0][0][n][uu]) +
             __bfloat162float(g_hbf[dir][0][1][n][uu]);
}

// =====================================================================
extern "C" void kernel_launch(void* const* d_in, const int* in_sizes, int n_in,
                              void* d_out, int out_size)
{
    (void)in_sizes; (void)n_in; (void)out_size;
    const int*   x    = (const int*)  d_in[0];
    const float* emb  = (const float*)d_in[1];
    const float* W_f  = (const float*)d_in[2];
    const float* U_f  = (const float*)d_in[3];
    const float* b_f  = (const float*)d_in[4];
    const float* W_b  = (const float*)d_in[5];
    const float* U_b  = (const float*)d_in[6];
    const float* b_b  = (const float*)d_in[7];
    float* out = (float*)d_out;

    static bool attr_done = false;
    if (!attr_done) {
        cudaFuncSetAttribute(step_kernel,
            cudaFuncAttributeMaxDynamicSharedMemorySize, STEP_SMEM);
        cudaFuncSetAttribute(proj_mma_kernel,
            cudaFuncAttributeMaxDynamicSharedMemorySize, PROJ_SMEM);
        attr_done = true;
    }

    conv_u_kernel<<<dim3(G4, 2), 128>>>(U_f, U_b);
    conv_w_kernel<<<dim3(G4, 2), 128>>>(W_f, W_b);

    dim3 pgrid(NSEQ, G4 / 128, 2);
    proj_mma_kernel<<<pgrid, 256, PROJ_SMEM>>>(x, emb, b_f, b_b);

    dim3 sgrid(NSEQ / MTILE, G4 / NTILE, 2);   // (4, 16, 2)
    for (int t = 0; t < TSEQ; t++)
        step_kernel<<<sgrid, 256, STEP_SMEM>>>(x, t);

    copy_out_kernel<<<(NSEQ * 1024) / 256, 256>>>(out);
}

// round 10
// speedup vs baseline: 4.2266x; 1.2180x over previous
#include <cuda_runtime.h>
#include <cuda_bf16.h>
#include <math.h>
#include <stdint.h>

#define NSEQ  256     // B*S
#define TSEQ  128
#define EMBED 512
#define UNITS 512
#define G4    2048    // 4*UNITS
#define KDIM  512
#define KC    64      // k-chunk (bf16 elems) = 128B row
#define NCHUNK 8
#define MTILE 64      // step: rows per CTA
#define NTILE 128     // step: 32 units * 4 gates (permuted cols)

// ---------------- scratch (__device__ globals, allocation-free) ----------------
__device__ __align__(16) float g_xW[2][TSEQ][NSEQ][G4];               // 512 MB
__device__ __align__(16) __nv_bfloat16 g_hbf[2][2][2][NSEQ][UNITS];   // h hi/lo, dbl-buf
__device__ __align__(16) __nv_bfloat16 g_Ubf[2][2][G4][KDIM];         // U hi/lo, permuted
__device__ __align__(16) __nv_bfloat16 g_Wbf[2][2][G4][KDIM];         // W hi/lo, natural
__device__ __align__(16) __nv_bfloat16 g_xE[2][NSEQ * TSEQ][EMBED];   // emb hi/lo, 64 MB
__device__ __align__(16) float g_c[2][2][NSEQ][UNITS];

// ---------------- helpers ----------------
__device__ __forceinline__ uint32_t smem_u32(const void* p) {
    uint32_t a;
    asm("{ .reg .u64 t; cvta.to.shared.u64 t, %1; cvt.u32.u64 %0, t; }" : "=r"(a) : "l"(p));
    return a;
}
#define SWZ(r, kb) (((r) * 128) + ((kb) ^ (((r) & 7) << 4)))

#define LDSM_X4(r0, r1, r2, r3, addr) \
    asm volatile("ldmatrix.sync.aligned.m8n8.x4.shared.b16 {%0,%1,%2,%3}, [%4];" \
        : "=r"(r0), "=r"(r1), "=r"(r2), "=r"(r3) : "r"(addr))

#define MMA16816(d, a, b0, b1) \
    asm volatile("mma.sync.aligned.m16n8k16.row.col.f32.bf16.bf16.f32 " \
        "{%0,%1,%2,%3}, {%4,%5,%6,%7}, {%8,%9}, {%0,%1,%2,%3};" \
        : "+f"((d)[0]), "+f"((d)[1]), "+f"((d)[2]), "+f"((d)[3]) \
        : "r"((a)[0]), "r"((a)[1]), "r"((a)[2]), "r"((a)[3]), "r"(b0), "r"(b1))

#define CP_A16(dst, src) \
    asm volatile("cp.async.cg.shared.global [%0], [%1], 16;" \
        :: "r"(dst), "l"(__cvta_generic_to_global(src)) : "memory")
#define CP_COMMIT() asm volatile("cp.async.commit_group;" ::: "memory")
#define CP_WAIT(n)  asm volatile("cp.async.wait_group %0;" :: "n"(n) : "memory")

// stage layouts (48KB per stage, two stages -> 96KB dynamic smem)
// step:  A(h) 64 rows  hi/lo, B(U) 128 rows hi/lo
#define S_A_HI 0
#define S_A_LO 8192
#define S_B_HI 16384
#define S_B_LO 32768
// proj:  A(xE) 128 rows hi/lo, B(W) 64 rows hi/lo
#define P_A_HI 0
#define P_A_LO 16384
#define P_B_HI 32768
#define P_B_LO 40960
#define STAGE_SZ 49152
#define PIPE_SMEM (2 * STAGE_SZ)

// =====================================================================
// conv kernels: fp32 -> bf16 hi/lo split.
// =====================================================================
__global__ void conv_u_kernel(const float* __restrict__ U_f,
                              const float* __restrict__ U_b)
{
    const int c   = blockIdx.x;
    const int dir = blockIdx.y;
    const float* __restrict__ U = dir ? U_b : U_f;
    const int g = c >> 9, u = c & 511;
    const int np = 4 * u + g;                 // gate-permuted col
    for (int k = threadIdx.x; k < KDIM; k += blockDim.x) {
        float v = U[(size_t)k * G4 + c];
        __nv_bfloat16 hi = __float2bfloat16(v);
        g_Ubf[dir][0][np][k] = hi;
        g_Ubf[dir][1][np][k] = __float2bfloat16(v - __bfloat162float(hi));
    }
}

__global__ void conv_w_kernel(const float* __restrict__ W_f,
                              const float* __restrict__ W_b)
{
    const int c   = blockIdx.x;
    const int dir = blockIdx.y;
    const float* __restrict__ W = dir ? W_b : W_f;
    for (int k = threadIdx.x; k < KDIM; k += blockDim.x) {
        float v = W[(size_t)k * G4 + c];
        __nv_bfloat16 hi = __float2bfloat16(v);
        g_Wbf[dir][0][c][k] = hi;
        g_Wbf[dir][1][c][k] = __float2bfloat16(v - __bfloat162float(hi));
    }
}

// gathered embeddings -> bf16 hi/lo (dir-independent)
__global__ void conv_e_kernel(const int* __restrict__ x,
                              const float* __restrict__ emb)
{
    const int row = blockIdx.x;               // n*TSEQ + t, 0..32767
    const float* src = emb + (size_t)x[row] * EMBED;
    for (int k = threadIdx.x; k < EMBED; k += blockDim.x) {
        float v = src[k];
        __nv_bfloat16 hi = __float2bfloat16(v);
        g_xE[0][row][k] = hi;
        g_xE[1][row][k] = __float2bfloat16(v - __bfloat162float(hi));
    }
}

// =====================================================================
// Kernel 1: input projection via mma.sync bf16x3, cp.async double-buffered.
// Grid (256, 32, 2): M=128 (sequence n's tokens), N=64 cols, dir.
// 8 warps in 4x2, warp tile 32x32, hoisted fragments.
// =====================================================================
__global__ __launch_bounds__(256) void proj_mma_kernel(
    const float* __restrict__ b_f, const float* __restrict__ b_b)
{
    extern __shared__ char smem[];
    const uint32_t sb = smem_u32(smem);

    const int tid  = threadIdx.x;
    const int lane = tid & 31;
    const int wid  = tid >> 5;
    const int n    = blockIdx.x;
    const int c0   = blockIdx.y * 64;
    const int dir  = blockIdx.z;
    const float* __restrict__ bias = dir ? b_b : b_f;

    const int wm = (wid & 3) * 32;
    const int wn = (wid >> 2) * 32;

    float acc[2][2][2][4];                    // [mfrag][n16][n8][4]
    #pragma unroll
    for (int i = 0; i < 2; i++)
        #pragma unroll
        for (int g = 0; g < 2; g++)
            #pragma unroll
            for (int j = 0; j < 2; j++)
                #pragma unroll
                for (int q = 0; q < 4; q++) acc[i][g][j][q] = 0.f;

    const int a_ro  = lane & 15;
    const int a_kb  = (lane >> 4) * 16;
    const int b_ro  = (lane & 7) + (lane >> 4) * 8;
    const int b_kb  = ((lane >> 3) & 1) * 16;

    // copy coords: A 128 rows x 8 granules x 2 splits = 2048 (8/thread)
    const int ar = tid >> 3, acc16 = (tid & 7) * 16;
    const size_t arow0 = (size_t)n * TSEQ;    // base row in g_xE

    // ---- issue chunk 0 ----
    #pragma unroll
    for (int s = 0; s < 2; s++) {
        #pragma unroll
        for (int it = 0; it < 4; it++) {
            int r = ar + it * 32;
            CP_A16(sb + (s ? P_A_LO : P_A_HI) + SWZ(r, acc16),
                   (const char*)&g_xE[s][arow0 + r][0] + acc16);
        }
        #pragma unroll
        for (int it = 0; it < 2; it++) {
            int r = ar + it * 32;
            CP_A16(sb + (s ? P_B_LO : P_B_HI) + SWZ(r, acc16),
                   (const char*)&g_Wbf[dir][s][c0 + r][0] + acc16);
        }
    }
    CP_COMMIT();

    for (int kc = 0; kc < NCHUNK; kc++) {
        if (kc + 1 < NCHUNK) {
            const int sbase = ((kc + 1) & 1) * STAGE_SZ;
            const int kb = (kc + 1) * KC;
            #pragma unroll
            for (int s = 0; s < 2; s++) {
                #pragma unroll
                for (int it = 0; it < 4; it++) {
                    int r = ar + it * 32;
                    CP_A16(sb + sbase + (s ? P_A_LO : P_A_HI) + SWZ(r, acc16),
                           (const char*)&g_xE[s][arow0 + r][kb] + acc16);
                }
                #pragma unroll
                for (int it = 0; it < 2; it++) {
                    int r = ar + it * 32;
                    CP_A16(sb + sbase + (s ? P_B_LO : P_B_HI) + SWZ(r, acc16),
                           (const char*)&g_Wbf[dir][s][c0 + r][kb] + acc16);
                }
            }
            CP_COMMIT();
            CP_WAIT(1);
        } else {
            CP_WAIT(0);
        }
        __syncthreads();

        const uint32_t stg = sb + (kc & 1) * STAGE_SZ;
        #pragma unroll
        for (int ks = 0; ks < 4; ks++) {
            uint32_t ah[2][4], al[2][4], bh[2][4], bl[2][4];
            #pragma unroll
            for (int i = 0; i < 2; i++) {
                LDSM_X4(ah[i][0], ah[i][1], ah[i][2], ah[i][3],
                        stg + P_A_HI + SWZ(wm + i * 16 + a_ro, ks * 32 + a_kb));
                LDSM_X4(al[i][0], al[i][1], al[i][2], al[i][3],
                        stg + P_A_LO + SWZ(wm + i * 16 + a_ro, ks * 32 + a_kb));
            }
            #pragma unroll
            for (int g = 0; g < 2; g++) {
                LDSM_X4(bh[g][0], bh[g][1], bh[g][2], bh[g][3],
                        stg + P_B_HI + SWZ(wn + g * 16 + b_ro, ks * 32 + b_kb));
                LDSM_X4(bl[g][0], bl[g][1], bl[g][2], bl[g][3],
                        stg + P_B_LO + SWZ(wn + g * 16 + b_ro, ks * 32 + b_kb));
            }
            #pragma unroll
            for (int i = 0; i < 2; i++)
                #pragma unroll
                for (int g = 0; g < 2; g++)
                    #pragma unroll
                    for (int j = 0; j < 2; j++) {
                        MMA16816(acc[i][g][j], ah[i], bh[g][2 * j], bh[g][2 * j + 1]);
                        MMA16816(acc[i][g][j], ah[i], bl[g][2 * j], bl[g][2 * j + 1]);
                        MMA16816(acc[i][g][j], al[i], bh[g][2 * j], bh[g][2 * j + 1]);
                    }
        }
        if (kc + 1 < NCHUNK) __syncthreads();
    }

    // ---- epilogue: bias + store to g_xW (dir-reversed rows) ----
    #pragma unroll
    for (int i = 0; i < 2; i++)
        #pragma unroll
        for (int g = 0; g < 2; g++)
            #pragma unroll
            for (int j = 0; j < 2; j++) {
                int col = c0 + wn + g * 16 + j * 8 + (lane & 3) * 2;
                float bi0 = bias[col], bi1 = bias[col + 1];
                int r0 = wm + i * 16 + (lane >> 2);
                int r1 = r0 + 8;
                int ts0 = dir ? (TSEQ - 1 - r0) : r0;
                int ts1 = dir ? (TSEQ - 1 - r1) : r1;
                *(float2*)&g_xW[dir][ts0][n][col] =
                    make_float2(acc[i][g][j][0] + bi0, acc[i][g][j][1] + bi1);
                *(float2*)&g_xW[dir][ts1][n][col] =
                    make_float2(acc[i][g][j][2] + bi0, acc[i][g][j][3] + bi1);
            }
}

// =====================================================================
// Kernel 2: one LSTM timestep via mma.sync bf16x3, cp.async pipeline.
// Grid (4, 16, 2): M=64, N=128 (32 units x 4 gates), dir.
// 8 warps in 2x4, warp tile 32x32, hoisted fragments.
// =====================================================================
__global__ __launch_bounds__(256) void step_kernel(const int* __restrict__ x, int t)
{
    extern __shared__ char smem[];
    const uint32_t sb = smem_u32(smem);

    const int tid  = threadIdx.x;
    const int lane = tid & 31;
    const int wid  = tid >> 5;
    const int dir  = blockIdx.z;
    const int m0   = blockIdx.x * MTILE;
    const int ub0  = blockIdx.y * 32;
    const int np0  = blockIdx.y * NTILE;
    const int pr   = t & 1, pw = pr ^ 1;

    float* zs = (float*)smem;                 // overlays stage 0 (32 KB)

    if (t > 0) {
        const int wm = (wid & 1) * 32;
        const int wn = (wid >> 1) * 32;

        float acc[2][2][2][4];
        #pragma unroll
        for (int i = 0; i < 2; i++)
            #pragma unroll
            for (int g = 0; g < 2; g++)
                #pragma unroll
                for (int j = 0; j < 2; j++)
                    #pragma unroll
                    for (int q = 0; q < 4; q++) acc[i][g][j][q] = 0.f;

        const int a_ro  = lane & 15;
        const int a_kb  = (lane >> 4) * 16;
        const int b_ro  = (lane & 7) + (lane >> 4) * 8;
        const int b_kb  = ((lane >> 3) & 1) * 16;

        const int ar = tid >> 3, acc16 = (tid & 7) * 16;

        // ---- issue chunk 0 ----
        #pragma unroll
        for (int s = 0; s < 2; s++) {
            #pragma unroll
            for (int it = 0; it < 2; it++) {
                int r = ar + it * 32;
                CP_A16(sb + (s ? S_A_LO : S_A_HI) + SWZ(r, acc16),
                       (const char*)&g_hbf[dir][pr][s][m0 + r][0] + acc16);
            }
            #pragma unroll
            for (int it = 0; it < 4; it++) {
                int r = ar + it * 32;
                CP_A16(sb + (s ? S_B_LO : S_B_HI) + SWZ(r, acc16),
                       (const char*)&g_Ubf[dir][s][np0 + r][0] + acc16);
            }
        }
        CP_COMMIT();

        for (int kc = 0; kc < NCHUNK; kc++) {
            if (kc + 1 < NCHUNK) {
                const int sbase = ((kc + 1) & 1) * STAGE_SZ;
                const int kb = (kc + 1) * KC;
                #pragma unroll
                for (int s = 0; s < 2; s++) {
                    #pragma unroll
                    for (int it = 0; it < 2; it++) {
                        int r = ar + it * 32;
                        CP_A16(sb + sbase + (s ? S_A_LO : S_A_HI) + SWZ(r, acc16),
                               (const char*)&g_hbf[dir][pr][s][m0 + r][kb] + acc16);
                    }
                    #pragma unroll
                    for (int it = 0; it < 4; it++) {
                        int r = ar + it * 32;
                        CP_A16(sb + sbase + (s ? S_B_LO : S_B_HI) + SWZ(r, acc16),
                               (const char*)&g_Ubf[dir][s][np0 + r][kb] + acc16);
                    }
                }
                CP_COMMIT();
                CP_WAIT(1);
            } else {
                CP_WAIT(0);
            }
            __syncthreads();

            const uint32_t stg = sb + (kc & 1) * STAGE_SZ;
            #pragma unroll
            for (int ks = 0; ks < 4; ks++) {
                uint32_t ah[2][4], al[2][4], bh[2][4], bl[2][4];
                #pragma unroll
                for (int i = 0; i < 2; i++) {
                    LDSM_X4(ah[i][0], ah[i][1], ah[i][2], ah[i][3],
                            stg + S_A_HI + SWZ(wm + i * 16 + a_ro, ks * 32 + a_kb));
                    LDSM_X4(al[i][0], al[i][1], al[i][2], al[i][3],
                            stg + S_A_LO + SWZ(wm + i * 16 + a_ro, ks * 32 + a_kb));
                }
                #pragma unroll
                for (int g = 0; g < 2; g++) {
                    LDSM_X4(bh[g][0], bh[g][1], bh[g][2], bh[g][3],
                            stg + S_B_HI + SWZ(wn + g * 16 + b_ro, ks * 32 + b_kb));
                    LDSM_X4(bl[g][0], bl[g][1], bl[g][2], bl[g][3],
                            stg + S_B_LO + SWZ(wn + g * 16 + b_ro, ks * 32 + b_kb));
                }
                #pragma unroll
                for (int i = 0; i < 2; i++)
                    #pragma unroll
                    for (int g = 0; g < 2; g++)
                        #pragma unroll
                        for (int j = 0; j < 2; j++) {
                            MMA16816(acc[i][g][j], ah[i], bh[g][2 * j], bh[g][2 * j + 1]);
                            MMA16816(acc[i][g][j], ah[i], bl[g][2 * j], bl[g][2 * j + 1]);
                            MMA16816(acc[i][g][j], al[i], bh[g][2 * j], bh[g][2 * j + 1]);
                        }
            }
            if (kc + 1 < NCHUNK) __syncthreads();
        }

        // ---- write z tile to smem (overlays stage 0; last MMAs read stage 1) ----
        #pragma unroll
        for (int i = 0; i < 2; i++)
            #pragma unroll
            for (int g = 0; g < 2; g++)
                #pragma unroll
                for (int j = 0; j < 2; j++) {
                    int r = wm + i * 16 + (lane >> 2);
                    int c = wn + g * 16 + j * 8 + (lane & 3) * 2;
                    *(float2*)&zs[r * 128 + c] =
                        make_float2(acc[i][g][j][0], acc[i][g][j][1]);
                    *(float2*)&zs[(r + 8) * 128 + c] =
                        make_float2(acc[i][g][j][2], acc[i][g][j][3]);
                }
        __syncthreads();
    } else {
        #pragma unroll
        for (int i = 0; i < 32; i++) zs[tid + i * 256] = 0.f;
        __syncthreads();
    }

    // ---------------- gate epilogue: 64 rows x 32 units ----------------
    const float* xw = &g_xW[dir][t][0][0];
    const int tt = dir ? (TSEQ - 1 - t) : t;
    #pragma unroll
    for (int i = 0; i < 8; i++) {
        int idx = tid + i * 256;
        int r = idx >> 5, ul = idx & 31;
        int gr = m0 + r, gu = ub0 + ul;
        const float* xwr = xw + (size_t)gr * G4;
        float zi = zs[r * 128 + 4 * ul + 0] + xwr[gu];
        float zf = zs[r * 128 + 4 * ul + 1] + xwr[512 + gu];
        float zg = zs[r * 128 + 4 * ul + 2] + xwr[1024 + gu];
        float zo = zs[r * 128 + 4 * ul + 3] + xwr[1536 + gu];
        float ig = 1.f / (1.f + expf(-zi));
        float fg = 1.f / (1.f + expf(-zf));
        float gg = tanhf(zg);
        float og = 1.f / (1.f + expf(-zo));
        float cold = (t > 0) ? g_c[dir][pr][gr][gu] : 0.f;
        float cn = fg * cold + ig * gg;
        float hn = og * tanhf(cn);
        bool msk = x[gr * TSEQ + tt] != 0;

        __nv_bfloat16 oh = __float2bfloat16(0.f), ol = oh;
        if (t > 0) { oh = g_hbf[dir][pr][0][gr][gu]; ol = g_hbf[dir][pr][1][gr][gu]; }
        __nv_bfloat16 nh, nl;
        if (msk) {
            nh = __float2bfloat16(hn);
            nl = __float2bfloat16(hn - __bfloat162float(nh));
        } else { nh = oh; nl = ol; }
        g_c[dir][pw][gr][gu] = msk ? cn : cold;
        g_hbf[dir][pw][0][gr][gu] = nh;
        g_hbf[dir][pw][1][gr][gu] = nl;
    }
}

// =====================================================================
// Kernel 3: concat [h_fwd, h_bwd] -> out fp32 (final state in buf 0).
// =====================================================================
__global__ void copy_out_kernel(float* __restrict__ out)
{
    int i = blockIdx.x * 256 + threadIdx.x;
    int n   = i >> 10;
    int u   = i & 1023;
    int dir = u >> 9;
    int uu  = u & 511;
    out[i] = __bfloat162float(g_hbf[dir][0][0][n][uu]) +
             __bfloat162float(g_hbf[dir][0][1][n][uu]);
}

// =====================================================================
extern "C" void kernel_launch(void* const* d_in, const int* in_sizes, int n_in,
                              void* d_out, int out_size)
{
    (void)in_sizes; (void)n_in; (void)out_size;
    const int*   x    = (const int*)  d_in[0];
    const float* emb  = (const float*)d_in[1];
    const float* W_f  = (const float*)d_in[2];
    const float* U_f  = (const float*)d_in[3];
    const float* b_f  = (const float*)d_in[4];
    const float* W_b  = (const float*)d_in[5];
    const float* U_b  = (const float*)d_in[6];
    const float* b_b  = (const float*)d_in[7];
    float* out = (float*)d_out;

    static bool attr_done = false;
    if (!attr_done) {
        cudaFuncSetAttribute(step_kernel,
            cudaFuncAttributeMaxDynamicSharedMemorySize, PIPE_SMEM);
        cudaFuncSetAttribute(proj_mma_kernel,
            cudaFuncAttributeMaxDynamicSharedMemorySize, PIPE_SMEM);
        attr_done = true;
    }

    conv_u_kernel<<<dim3(G4, 2), 128>>>(U_f, U_b);
    conv_w_kernel<<<dim3(G4, 2), 128>>>(W_f, W_b);
    conv_e_kernel<<<NSEQ * TSEQ, 256>>>(x, emb);

    dim3 pgrid(NSEQ, G4 / 64, 2);              // (256, 32, 2)
    proj_mma_kernel<<<pgrid, 256, PIPE_SMEM>>>(b_f, b_b);

    dim3 sgrid(NSEQ / MTILE, G4 / NTILE, 2);   // (4, 16, 2)
    for (int t = 0; t < TSEQ; t++)
        step_kernel<<<sgrid, 256, PIPE_SMEM>>>(x, t);

    copy_out_kernel<<<(NSEQ * 1024) / 256, 256>>>(out);
}

// round 11
// speedup vs baseline: 4.3681x; 1.0335x over previous
#include <cuda_runtime.h>
#include <cuda_bf16.h>
#include <math.h>
#include <stdint.h>

#define NSEQ  256     // B*S
#define TSEQ  128
#define EMBED 512
#define UNITS 512
#define G4    2048    // 4*UNITS
#define KDIM  512
#define KC    64      // k-chunk (bf16 elems) = 128B row
#define NCHUNK 8
#define NCTA  128     // persistent grid size

// ---------------- scratch (__device__ globals, allocation-free) ----------------
__device__ __align__(16) float g_xW[2][TSEQ][NSEQ][G4];               // 512 MB
__device__ __align__(16) __nv_bfloat16 g_hbf[2][2][2][NSEQ][UNITS];   // h hi/lo, dbl-buf
__device__ __align__(16) __nv_bfloat16 g_Ubf[2][2][G4][KDIM];         // U hi/lo, permuted
__device__ __align__(16) __nv_bfloat16 g_Wbf[2][2][G4][KDIM];         // W hi/lo, natural
__device__ __align__(16) __nv_bfloat16 g_xE[2][NSEQ * TSEQ][EMBED];   // emb hi/lo, 64 MB
__device__ __align__(16) float g_c[2][2][NSEQ][UNITS];
__device__ unsigned g_bar_cnt;                                        // grid barrier

// ---------------- helpers ----------------
__device__ __forceinline__ uint32_t smem_u32(const void* p) {
    uint32_t a;
    asm("{ .reg .u64 t; cvta.to.shared.u64 t, %1; cvt.u32.u64 %0, t; }" : "=r"(a) : "l"(p));
    return a;
}
#define SWZ(r, kb) (((r) * 128) + ((kb) ^ (((r) & 7) << 4)))

#define LDSM_X4(r0, r1, r2, r3, addr) \
    asm volatile("ldmatrix.sync.aligned.m8n8.x4.shared.b16 {%0,%1,%2,%3}, [%4];" \
        : "=r"(r0), "=r"(r1), "=r"(r2), "=r"(r3) : "r"(addr))

#define MMA16816(d, a, b0, b1) \
    asm volatile("mma.sync.aligned.m16n8k16.row.col.f32.bf16.bf16.f32 " \
        "{%0,%1,%2,%3}, {%4,%5,%6,%7}, {%8,%9}, {%0,%1,%2,%3};" \
        : "+f"((d)[0]), "+f"((d)[1]), "+f"((d)[2]), "+f"((d)[3]) \
        : "r"((a)[0]), "r"((a)[1]), "r"((a)[2]), "r"((a)[3]), "r"(b0), "r"(b1))

#define CP_A16(dst, src) \
    asm volatile("cp.async.cg.shared.global [%0], [%1], 16;" \
        :: "r"(dst), "l"(__cvta_generic_to_global(src)) : "memory")
#define CP_COMMIT() asm volatile("cp.async.commit_group;" ::: "memory")
#define CP_WAIT(n)  asm volatile("cp.async.wait_group %0;" :: "n"(n) : "memory")

// proj stage layout (48KB per stage, two stages)
#define P_A_HI 0
#define P_A_LO 16384
#define P_B_HI 32768
#define P_B_LO 40960
#define STAGE_SZ 49152
#define PIPE_SMEM (2 * STAGE_SZ)

// persistent step kernel smem: U-resident 128KB + 2 A stages 64KB
#define S2_U_OFF 0              // [split][chunk][64 rows][128B]
#define S2_A_OFF 131072         // stage*32768 + split*16384 + SWZ(r,kb)
#define S2_SMEM  196608

// =====================================================================
// conv kernels: fp32 -> bf16 hi/lo split.
// =====================================================================
__global__ void conv_u_kernel(const float* __restrict__ U_f,
                              const float* __restrict__ U_b)
{
    const int c   = blockIdx.x;
    const int dir = blockIdx.y;
    const float* __restrict__ U = dir ? U_b : U_f;
    const int g = c >> 9, u = c & 511;
    const int np = 4 * u + g;                 // gate-permuted col
    for (int k = threadIdx.x; k < KDIM; k += blockDim.x) {
        float v = U[(size_t)k * G4 + c];
        __nv_bfloat16 hi = __float2bfloat16(v);
        g_Ubf[dir][0][np][k] = hi;
        g_Ubf[dir][1][np][k] = __float2bfloat16(v - __bfloat162float(hi));
    }
}

__global__ void conv_w_kernel(const float* __restrict__ W_f,
                              const float* __restrict__ W_b)
{
    const int c   = blockIdx.x;
    const int dir = blockIdx.y;
    const float* __restrict__ W = dir ? W_b : W_f;
    for (int k = threadIdx.x; k < KDIM; k += blockDim.x) {
        float v = W[(size_t)k * G4 + c];
        __nv_bfloat16 hi = __float2bfloat16(v);
        g_Wbf[dir][0][c][k] = hi;
        g_Wbf[dir][1][c][k] = __float2bfloat16(v - __bfloat162float(hi));
    }
}

__global__ void conv_e_kernel(const int* __restrict__ x,
                              const float* __restrict__ emb)
{
    const int row = blockIdx.x;               // n*TSEQ + t
    const float* src = emb + (size_t)x[row] * EMBED;
    for (int k = threadIdx.x; k < EMBED; k += blockDim.x) {
        float v = src[k];
        __nv_bfloat16 hi = __float2bfloat16(v);
        g_xE[0][row][k] = hi;
        g_xE[1][row][k] = __float2bfloat16(v - __bfloat162float(hi));
    }
}

// =====================================================================
// Kernel 1: input projection via mma.sync bf16x3, cp.async double-buffered.
// Grid (256, 32, 2): M=128, N=64, dir. 8 warps 4x2, warp tile 32x32.
// (unchanged from R10 — measured tensor=75.5%)
// =====================================================================
__global__ __launch_bounds__(256) void proj_mma_kernel(
    const float* __restrict__ b_f, const float* __restrict__ b_b)
{
    extern __shared__ char smem[];
    const uint32_t sb = smem_u32(smem);

    const int tid  = threadIdx.x;
    const int lane = tid & 31;
    const int wid  = tid >> 5;
    const int n    = blockIdx.x;
    const int c0   = blockIdx.y * 64;
    const int dir  = blockIdx.z;
    const float* __restrict__ bias = dir ? b_b : b_f;

    const int wm = (wid & 3) * 32;
    const int wn = (wid >> 2) * 32;

    float acc[2][2][2][4];
    #pragma unroll
    for (int i = 0; i < 2; i++)
        #pragma unroll
        for (int g = 0; g < 2; g++)
            #pragma unroll
            for (int j = 0; j < 2; j++)
                #pragma unroll
                for (int q = 0; q < 4; q++) acc[i][g][j][q] = 0.f;

    const int a_ro  = lane & 15;
    const int a_kb  = (lane >> 4) * 16;
    const int b_ro  = (lane & 7) + (lane >> 4) * 8;
    const int b_kb  = ((lane >> 3) & 1) * 16;

    const int ar = tid >> 3, acc16 = (tid & 7) * 16;
    const size_t arow0 = (size_t)n * TSEQ;

    #pragma unroll
    for (int s = 0; s < 2; s++) {
        #pragma unroll
        for (int it = 0; it < 4; it++) {
            int r = ar + it * 32;
            CP_A16(sb + (s ? P_A_LO : P_A_HI) + SWZ(r, acc16),
                   (const char*)&g_xE[s][arow0 + r][0] + acc16);
        }
        #pragma unroll
        for (int it = 0; it < 2; it++) {
            int r = ar + it * 32;
            CP_A16(sb + (s ? P_B_LO : P_B_HI) + SWZ(r, acc16),
                   (const char*)&g_Wbf[dir][s][c0 + r][0] + acc16);
        }
    }
    CP_COMMIT();

    for (int kc = 0; kc < NCHUNK; kc++) {
        if (kc + 1 < NCHUNK) {
            const int sbase = ((kc + 1) & 1) * STAGE_SZ;
            const int kb = (kc + 1) * KC;
            #pragma unroll
            for (int s = 0; s < 2; s++) {
                #pragma unroll
                for (int it = 0; it < 4; it++) {
                    int r = ar + it * 32;
                    CP_A16(sb + sbase + (s ? P_A_LO : P_A_HI) + SWZ(r, acc16),
                           (const char*)&g_xE[s][arow0 + r][kb] + acc16);
                }
                #pragma unroll
                for (int it = 0; it < 2; it++) {
                    int r = ar + it * 32;
                    CP_A16(sb + sbase + (s ? P_B_LO : P_B_HI) + SWZ(r, acc16),
                           (const char*)&g_Wbf[dir][s][c0 + r][kb] + acc16);
                }
            }
            CP_COMMIT();
            CP_WAIT(1);
        } else {
            CP_WAIT(0);
        }
        __syncthreads();

        const uint32_t stg = sb + (kc & 1) * STAGE_SZ;
        #pragma unroll
        for (int ks = 0; ks < 4; ks++) {
            uint32_t ah[2][4], al[2][4], bh[2][4], bl[2][4];
            #pragma unroll
            for (int i = 0; i < 2; i++) {
                LDSM_X4(ah[i][0], ah[i][1], ah[i][2], ah[i][3],
                        stg + P_A_HI + SWZ(wm + i * 16 + a_ro, ks * 32 + a_kb));
                LDSM_X4(al[i][0], al[i][1], al[i][2], al[i][3],
                        stg + P_A_LO + SWZ(wm + i * 16 + a_ro, ks * 32 + a_kb));
            }
            #pragma unroll
            for (int g = 0; g < 2; g++) {
                LDSM_X4(bh[g][0], bh[g][1], bh[g][2], bh[g][3],
                        stg + P_B_HI + SWZ(wn + g * 16 + b_ro, ks * 32 + b_kb));
                LDSM_X4(bl[g][0], bl[g][1], bl[g][2], bl[g][3],
                        stg + P_B_LO + SWZ(wn + g * 16 + b_ro, ks * 32 + b_kb));
            }
            #pragma unroll
            for (int i = 0; i < 2; i++)
                #pragma unroll
                for (int g = 0; g < 2; g++)
                    #pragma unroll
                    for (int j = 0; j < 2; j++) {
                        MMA16816(acc[i][g][j], ah[i], bh[g][2 * j], bh[g][2 * j + 1]);
                        MMA16816(acc[i][g][j], ah[i], bl[g][2 * j], bl[g][2 * j + 1]);
                        MMA16816(acc[i][g][j], al[i], bh[g][2 * j], bh[g][2 * j + 1]);
                    }
        }
        if (kc + 1 < NCHUNK) __syncthreads();
    }

    #pragma unroll
    for (int i = 0; i < 2; i++)
        #pragma unroll
        for (int g = 0; g < 2; g++)
            #pragma unroll
            for (int j = 0; j < 2; j++) {
                int col = c0 + wn + g * 16 + j * 8 + (lane & 3) * 2;
                float bi0 = bias[col], bi1 = bias[col + 1];
                int r0 = wm + i * 16 + (lane >> 2);
                int r1 = r0 + 8;
                int ts0 = dir ? (TSEQ - 1 - r0) : r0;
                int ts1 = dir ? (TSEQ - 1 - r1) : r1;
                *(float2*)&g_xW[dir][ts0][n][col] =
                    make_float2(acc[i][g][j][0] + bi0, acc[i][g][j][1] + bi1);
                *(float2*)&g_xW[dir][ts1][n][col] =
                    make_float2(acc[i][g][j][2] + bi0, acc[i][g][j][3] + bi1);
            }
}

// =====================================================================
// Kernel 2: PERSISTENT recurrence — all 128 timesteps in one launch.
// Grid 128 CTAs (co-resident): bid -> (dir, mtile, ntile).
// Each CTA: M=128 rows x N=64 permuted cols (16 units x 4 gates).
// U slice held in smem for the whole kernel; h streamed per step via
// cp.async; hand-rolled grid barrier between steps.
// =====================================================================
__global__ __launch_bounds__(256) void persist_step_kernel(const int* __restrict__ x)
{
    extern __shared__ char smem[];
    const uint32_t sb = smem_u32(smem);

    const int tid  = threadIdx.x;
    const int lane = tid & 31;
    const int wid  = tid >> 5;
    const int bid  = blockIdx.x;
    const int dir   = bid >> 6;
    const int mtile = (bid >> 5) & 1;
    const int ntile = bid & 31;
    const int m0  = mtile * 128;
    const int np0 = ntile * 64;
    const int ub0 = ntile * 16;

    float* zs = (float*)(smem + S2_A_OFF);    // 128x64 fp32, overlays A stage 0

    // ---- one-time: preload U slice (hi/lo, all 8 chunks) into smem ----
    // 8192 granules of 16B: j -> split, chunk, row, g8
    #pragma unroll
    for (int it = 0; it < 32; it++) {
        int j = tid + it * 256;
        int split = j >> 12;
        int kc    = (j >> 9) & 7;
        int row   = (j >> 3) & 63;
        int g8    = (j & 7) * 16;
        CP_A16(sb + S2_U_OFF + split * 65536 + kc * 8192 + SWZ(row, g8),
               (const char*)&g_Ubf[dir][split][np0 + row][kc * KC] + g8);
    }
    CP_COMMIT();
    CP_WAIT(0);
    __syncthreads();

    const int wm = (wid & 3) * 32;            // 4 M-warps x 2 N-warps
    const int wn = (wid >> 2) * 32;
    const int a_ro  = lane & 15;
    const int a_kb  = (lane >> 4) * 16;
    const int b_ro  = (lane & 7) + (lane >> 4) * 8;
    const int b_kb  = ((lane >> 3) & 1) * 16;
    const int ar = tid >> 3, acc16 = (tid & 7) * 16;

    for (int t = 0; t < TSEQ; t++) {
        const int pr = t & 1, pw = pr ^ 1;

        if (t > 0) {
            float acc[2][2][2][4];
            #pragma unroll
            for (int i = 0; i < 2; i++)
                #pragma unroll
                for (int g = 0; g < 2; g++)
                    #pragma unroll
                    for (int j = 0; j < 2; j++)
                        #pragma unroll
                        for (int q = 0; q < 4; q++) acc[i][g][j][q] = 0.f;

            // issue A chunk 0: 128 rows x 8 granules x 2 splits = 2048
            #pragma unroll
            for (int it = 0; it < 8; it++) {
                int j = tid + it * 256;
                int split = j >> 10;
                int r     = (j >> 3) & 127;
                int g8    = (j & 7) * 16;
                CP_A16(sb + S2_A_OFF + split * 16384 + SWZ(r, g8),
                       (const char*)&g_hbf[dir][pr][split][m0 + r][0] + g8);
            }
            CP_COMMIT();

            for (int kc = 0; kc < NCHUNK; kc++) {
                if (kc + 1 < NCHUNK) {
                    const int sbase = ((kc + 1) & 1) * 32768;
                    const int kb = (kc + 1) * KC;
                    #pragma unroll
                    for (int it = 0; it < 8; it++) {
                        int j = tid + it * 256;
                        int split = j >> 10;
                        int r     = (j >> 3) & 127;
                        int g8    = (j & 7) * 16;
                        CP_A16(sb + S2_A_OFF + sbase + split * 16384 + SWZ(r, g8),
                               (const char*)&g_hbf[dir][pr][split][m0 + r][kb] + g8);
                    }
                    CP_COMMIT();
                    CP_WAIT(1);
                } else {
                    CP_WAIT(0);
                }
                __syncthreads();

                const uint32_t sa = sb + S2_A_OFF + (kc & 1) * 32768;
                const uint32_t su = sb + S2_U_OFF + kc * 8192;
                #pragma unroll
                for (int ks = 0; ks < 4; ks++) {
                    uint32_t ah[2][4], al[2][4], bh[2][4], bl[2][4];
                    #pragma unroll
                    for (int i = 0; i < 2; i++) {
                        LDSM_X4(ah[i][0], ah[i][1], ah[i][2], ah[i][3],
                                sa + SWZ(wm + i * 16 + a_ro, ks * 32 + a_kb));
                        LDSM_X4(al[i][0], al[i][1], al[i][2], al[i][3],
                                sa + 16384 + SWZ(wm + i * 16 + a_ro, ks * 32 + a_kb));
                    }
                    #pragma unroll
                    for (int g = 0; g < 2; g++) {
                        LDSM_X4(bh[g][0], bh[g][1], bh[g][2], bh[g][3],
                                su + SWZ(wn + g * 16 + b_ro, ks * 32 + b_kb));
                        LDSM_X4(bl[g][0], bl[g][1], bl[g][2], bl[g][3],
                                su + 65536 + SWZ(wn + g * 16 + b_ro, ks * 32 + b_kb));
                    }
                    #pragma unroll
                    for (int i = 0; i < 2; i++)
                        #pragma unroll
                        for (int g = 0; g < 2; g++)
                            #pragma unroll
                            for (int j = 0; j < 2; j++) {
                                MMA16816(acc[i][g][j], ah[i], bh[g][2 * j], bh[g][2 * j + 1]);
                                MMA16816(acc[i][g][j], ah[i], bl[g][2 * j], bl[g][2 * j + 1]);
                                MMA16816(acc[i][g][j], al[i], bh[g][2 * j], bh[g][2 * j + 1]);
                            }
                }
                if (kc + 1 < NCHUNK) __syncthreads();
            }

            // write z (128x64) to smem; last MMAs read stage 1 (z covers stage 0)
            #pragma unroll
            for (int i = 0; i < 2; i++)
                #pragma unroll
                for (int g = 0; g < 2; g++)
                    #pragma unroll
                    for (int j = 0; j < 2; j++) {
                        int r = wm + i * 16 + (lane >> 2);
                        int c = wn + g * 16 + j * 8 + (lane & 3) * 2;
                        *(float2*)&zs[r * 64 + c] =
                            make_float2(acc[i][g][j][0], acc[i][g][j][1]);
                        *(float2*)&zs[(r + 8) * 64 + c] =
                            make_float2(acc[i][g][j][2], acc[i][g][j][3]);
                    }
            __syncthreads();
        } else {
            #pragma unroll
            for (int i = 0; i < 32; i++) zs[tid + i * 256] = 0.f;
            __syncthreads();
        }

        // ---- gate epilogue: 128 rows x 16 units, 8 items/thread ----
        const float* xw = &g_xW[dir][t][0][0];
        const int tt = dir ? (TSEQ - 1 - t) : t;
        #pragma unroll
        for (int i = 0; i < 8; i++) {
            int idx = tid + i * 256;
            int r = idx >> 4, ul = idx & 15;
            int gr = m0 + r, gu = ub0 + ul;
            const float* xwr = xw + (size_t)gr * G4;
            float4 z4 = *(const float4*)&zs[r * 64 + ul * 4];
            float zi = z4.x + xwr[gu];
            float zf = z4.y + xwr[512 + gu];
            float zg = z4.z + xwr[1024 + gu];
            float zo = z4.w + xwr[1536 + gu];
            float ig = 1.f / (1.f + expf(-zi));
            float fg = 1.f / (1.f + expf(-zf));
            float gg = tanhf(zg);
            float og = 1.f / (1.f + expf(-zo));
            float cold = (t > 0) ? g_c[dir][pr][gr][gu] : 0.f;
            float cn = fg * cold + ig * gg;
            float hn = og * tanhf(cn);
            bool msk = x[gr * TSEQ + tt] != 0;

            __nv_bfloat16 oh = __float2bfloat16(0.f), ol = oh;
            if (t > 0) { oh = g_hbf[dir][pr][0][gr][gu]; ol = g_hbf[dir][pr][1][gr][gu]; }
            __nv_bfloat16 nh, nl;
            if (msk) {
                nh = __float2bfloat16(hn);
                nl = __float2bfloat16(hn - __bfloat162float(nh));
            } else { nh = oh; nl = ol; }
            g_c[dir][pw][gr][gu] = msk ? cn : cold;
            g_hbf[dir][pw][0][gr][gu] = nh;
            g_hbf[dir][pw][1][gr][gu] = nl;
        }

        // ---- grid barrier: all CTAs finish step t before step t+1 ----
        __syncthreads();
        if (tid == 0) {
            __threadfence();
            atomicAdd(&g_bar_cnt, 1u);
            const unsigned target = (unsigned)NCTA * (unsigned)(t + 1);
            while (*((volatile unsigned*)&g_bar_cnt) < target) { }
            __threadfence();
        }
        __syncthreads();
    }

    // ---- exit round: reset counter for the next graph replay ----
    if (tid == 0) {
        atomicAdd(&g_bar_cnt, 1u);
        if (bid == 0) {
            const unsigned target = (unsigned)NCTA * (unsigned)TSEQ + (unsigned)NCTA;
            while (*((volatile unsigned*)&g_bar_cnt) < target) { }
            g_bar_cnt = 0;
            __threadfence();
        }
    }
}

// =====================================================================
// Kernel 3: concat [h_fwd, h_bwd] -> out fp32 (final state in buf 0).
// =====================================================================
__global__ void copy_out_kernel(float* __restrict__ out)
{
    int i = blockIdx.x * 256 + threadIdx.x;
    int n   = i >> 10;
    int u   = i & 1023;
    int dir = u >> 9;
    int uu  = u & 511;
    out[i] = __bfloat162float(g_hbf[dir][0][0][n][uu]) +
             __bfloat162float(g_hbf[dir][0][1][n][uu]);
}

// =====================================================================
extern "C" void kernel_launch(void* const* d_in, const int* in_sizes, int n_in,
                              void* d_out, int out_size)
{
    (void)in_sizes; (void)n_in; (void)out_size;
    const int*   x    = (const int*)  d_in[0];
    const float* emb  = (const float*)d_in[1];
    const float* W_f  = (const float*)d_in[2];
    const float* U_f  = (const float*)d_in[3];
    const float* b_f  = (const float*)d_in[4];
    const float* W_b  = (const float*)d_in[5];
    const float* U_b  = (const float*)d_in[6];
    const float* b_b  = (const float*)d_in[7];
    float* out = (float*)d_out;

    cudaFuncSetAttribute(proj_mma_kernel,
        cudaFuncAttributeMaxDynamicSharedMemorySize, PIPE_SMEM);
    cudaFuncSetAttribute(persist_step_kernel,
        cudaFuncAttributeMaxDynamicSharedMemorySize, S2_SMEM);

    conv_u_kernel<<<dim3(G4, 2), 128>>>(U_f, U_b);
    conv_w_kernel<<<dim3(G4, 2), 128>>>(W_f, W_b);
    conv_e_kernel<<<NSEQ * TSEQ, 256>>>(x, emb);

    dim3 pgrid(NSEQ, G4 / 64, 2);              // (256, 32, 2)
    proj_mma_kernel<<<pgrid, 256, PIPE_SMEM>>>(b_f, b_b);

    persist_step_kernel<<<NCTA, 256, S2_SMEM>>>(x);

    copy_out_kernel<<<(NSEQ * 1024) / 256, 256>>>(out);
}